// round 6
// baseline (speedup 1.0000x reference)
#include <cuda_runtime.h>
#include <math.h>
#include <stdint.h>

// Scratch (allocation-free rule: __device__ globals)
__device__ float g_dct[128 * 3 * 64];   // dct branch input, (b,c,8,8)
__device__ float g_grad[128 * 3 * 64];  // grad branch input, (b,c,8,8)

__device__ __forceinline__ uint64_t pack2(float lo, float hi) {
    uint64_t r;
    asm("mov.b64 %0, {%1, %2};" : "=l"(r) : "r"(__float_as_uint(lo)), "r"(__float_as_uint(hi)));
    return r;
}
__device__ __forceinline__ void unpack2(float& lo, float& hi, uint64_t v) {
    uint32_t a, b;
    asm("mov.b64 {%0, %1}, %2;" : "=r"(a), "=r"(b) : "l"(v));
    lo = __uint_as_float(a); hi = __uint_as_float(b);
}
__device__ __forceinline__ uint64_t fma2(uint64_t a, uint64_t b, uint64_t c) {
    uint64_t d;
    asm("fma.rn.f32x2 %0, %1, %2, %3;" : "=l"(d) : "l"(a), "l"(b), "l"(c));
    return d;
}

// ---------------------------------------------------------------------------
// Kernel 1: per (b,c) image: dct_in = A x A^T  and sampled-Sobel grad_in.
// A[o][j] = 0.5*sqrt(2/256) * sum_{k<25} scale(k) *
//           [cos(pi(2k+1)(32o+15)/512) + cos(pi(2k+1)(32o+16)/512)]
//           * cos(pi(2j+1)k/512)
// computed inline per block (Chebyshev recurrence, ~500 cyc).
// grid = 384 (= 128*3), block = 256
// ---------------------------------------------------------------------------
__global__ void __launch_bounds__(256) dct_grad_kernel(const float* __restrict__ x) {
    __shared__ float    Rf2[8][25];        // per-o weights
    __shared__ uint64_t Asd[256][8];       // A duplicated pairs (a,a)  (16 KB)
    __shared__ float    As2[8][256];       // A row-major for pass 2    (8 KB)
    __shared__ float    Tp[4][8][256];     // team partials / Ts        (32 KB)

    const int tid = threadIdx.x;
    const int blk = blockIdx.x;
    const float* __restrict__ xc = x + (size_t)blk * 65536;

    // --- inline A computation -------------------------------------------
    if (tid < 200) {
        const int o = tid / 25, k = tid % 25;
        float sk = (k == 0) ? sqrtf(1.0f / 256.0f) : sqrtf(2.0f / 256.0f);
        float si = sqrtf(2.0f / 256.0f);
        float tw = (float)(2 * k + 1) * (1.0f / 512.0f);   // exact
        float c0 = cospif(tw * (float)(32 * o + 15));
        float c1 = cospif(tw * (float)(32 * o + 16));
        Rf2[o][k] = 0.5f * si * sk * (c0 + c1);
    }
    __syncthreads();
    {
        const float th = (float)(2 * tid + 1) * (1.0f / 512.0f);  // exact
        float cp = cospif(th);
        const float twoc = 2.0f * cp;
        float cpp = 1.0f;
        float a[8];
#pragma unroll
        for (int o = 0; o < 8; o++) a[o] = fmaf(Rf2[o][1], cp, Rf2[o][0]);
#pragma unroll
        for (int k = 2; k < 25; k++) {
            float ck = fmaf(twoc, cp, -cpp);
#pragma unroll
            for (int o = 0; o < 8; o++) a[o] = fmaf(Rf2[o][k], ck, a[o]);
            cpp = cp; cp = ck;
        }
#pragma unroll
        for (int o = 0; o < 8; o++) {
            As2[o][tid] = a[o];
            Asd[tid][o] = pack2(a[o], a[o]);
        }
    }
    __syncthreads();

    // --- pass 1: T = A @ X, f32x2 packed FMA ----------------------------
    const int team = tid >> 6;         // 0..3 -> rows 64*team..64*team+63
    const int t64  = tid & 63;         // columns 4*t64..4*t64+3

    uint64_t acc2[8][2];
#pragma unroll
    for (int o = 0; o < 8; o++) { acc2[o][0] = 0ull; acc2[o][1] = 0ull; }

    const int mbase = team * 64;
#pragma unroll 8
    for (int mm = 0; mm < 64; mm++) {
        const int m = mbase + mm;
        float4 xv = reinterpret_cast<const float4*>(xc + (size_t)m * 256)[t64];
        uint64_t x01 = pack2(xv.x, xv.y);
        uint64_t x23 = pack2(xv.z, xv.w);
        ulonglong2 d01 = *reinterpret_cast<const ulonglong2*>(&Asd[m][0]);
        ulonglong2 d23 = *reinterpret_cast<const ulonglong2*>(&Asd[m][2]);
        ulonglong2 d45 = *reinterpret_cast<const ulonglong2*>(&Asd[m][4]);
        ulonglong2 d67 = *reinterpret_cast<const ulonglong2*>(&Asd[m][6]);
        acc2[0][0] = fma2(d01.x, x01, acc2[0][0]);
        acc2[0][1] = fma2(d01.x, x23, acc2[0][1]);
        acc2[1][0] = fma2(d01.y, x01, acc2[1][0]);
        acc2[1][1] = fma2(d01.y, x23, acc2[1][1]);
        acc2[2][0] = fma2(d23.x, x01, acc2[2][0]);
        acc2[2][1] = fma2(d23.x, x23, acc2[2][1]);
        acc2[3][0] = fma2(d23.y, x01, acc2[3][0]);
        acc2[3][1] = fma2(d23.y, x23, acc2[3][1]);
        acc2[4][0] = fma2(d45.x, x01, acc2[4][0]);
        acc2[4][1] = fma2(d45.x, x23, acc2[4][1]);
        acc2[5][0] = fma2(d45.y, x01, acc2[5][0]);
        acc2[5][1] = fma2(d45.y, x23, acc2[5][1]);
        acc2[6][0] = fma2(d67.x, x01, acc2[6][0]);
        acc2[6][1] = fma2(d67.x, x23, acc2[6][1]);
        acc2[7][0] = fma2(d67.y, x01, acc2[7][0]);
        acc2[7][1] = fma2(d67.y, x23, acc2[7][1]);
    }
#pragma unroll
    for (int o = 0; o < 8; o++) {
        float4 v;
        unpack2(v.x, v.y, acc2[o][0]);
        unpack2(v.z, v.w, acc2[o][1]);
        *reinterpret_cast<float4*>(&Tp[team][o][t64 * 4]) = v;
    }
    __syncthreads();

    // Reduce 4 team partials; alias Ts over Tp[0] (thread t only touches col t).
    float* TsF = &Tp[0][0][0];   // Ts[o][c] = TsF[o*256 + c]
    {
        float s[8];
#pragma unroll
        for (int o = 0; o < 8; o++)
            s[o] = Tp[0][o][tid] + Tp[1][o][tid] + Tp[2][o][tid] + Tp[3][o][tid];
#pragma unroll
        for (int o = 0; o < 8; o++) TsF[o * 256 + tid] = s[o];
    }
    __syncthreads();

    // --- pass 2: out = Ts @ A^T, 4 partials per output ------------------
    {
        const int outp = tid >> 2;          // 0..63
        const int part = tid & 3;
        const int oy = outp >> 3, ox = outp & 7;
        const float* __restrict__ tsr = TsF + oy * 256;
        const float* __restrict__ ar  = &As2[ox][0];
        float s = 0.0f;
        const int rot = (4 * outp + part) & 63;   // bank-conflict-free rotation
#pragma unroll 8
        for (int i = 0; i < 64; i++) {
            int j = part * 64 + ((i + rot) & 63);
            s = fmaf(tsr[j], ar[j], s);
        }
        s += __shfl_xor_sync(0xffffffffu, s, 1);
        s += __shfl_xor_sync(0xffffffffu, s, 2);
        if (part == 0) g_dct[blk * 64 + outp] = s;
    }

    // --- Sobel: 1 sample point per thread, butterfly over 4 ------------
    {
        const int cell = tid >> 2;          // 0..63
        const int pt = tid & 3;
        const int r = 32 * (cell >> 3) + 15 + (pt >> 1);
        const int c = 32 * (cell & 7) + 15 + (pt & 1);
        float p[3][3];
#pragma unroll
        for (int a = 0; a < 3; a++)
#pragma unroll
            for (int b = 0; b < 3; b++)
                p[a][b] = xc[(r - 1 + a) * 256 + (c - 1 + b)];
        float gx = (p[0][2] - p[0][0])
                 + 2.0f * (p[1][2] - p[1][0])
                 + (p[2][2] - p[2][0]);
        float gy = (p[2][0] - p[0][0])
                 + 2.0f * (p[2][1] - p[0][1])
                 + (p[2][2] - p[0][2]);
        float mag = sqrtf(gx * gx + gy * gy);
        mag += __shfl_xor_sync(0xffffffffu, mag, 1);
        mag += __shfl_xor_sync(0xffffffffu, mag, 2);
        if (pt == 0) g_grad[blk * 64 + cell] = 0.25f * mag;
    }
}

// ---------------------------------------------------------------------------
// Kernel 2: conv3x3 + BN + ReLU on both branches, fusion gate, classifier.
// grid = 128 (one block per batch), block = 256 (thread = (co, quarter))
// ---------------------------------------------------------------------------
__global__ void __launch_bounds__(256) head_kernel(
    const float* __restrict__ cw_d, const float* __restrict__ cb_d,
    const float* __restrict__ bg_d, const float* __restrict__ bb_d,
    const float* __restrict__ cw_g, const float* __restrict__ cb_g,
    const float* __restrict__ bg_g, const float* __restrict__ bb_g,
    const float* __restrict__ fw, const float* __restrict__ fb,
    const float* __restrict__ clsw, const float* __restrict__ clsb,
    float* __restrict__ out)
{
    __shared__ float tile[2][3][10][10];
    __shared__ float red[256];
    __shared__ float warpred[8][4];
    __shared__ float sfw[64];

    const int b = blockIdx.x;
    const int tid = threadIdx.x;

    for (int t = tid; t < 600; t += 256) {
        int br = t / 300, rem = t % 300;
        int c = rem / 100, yy = (rem % 100) / 10, xx = rem % 10;
        float v = 0.0f;
        if (yy >= 1 && yy <= 8 && xx >= 1 && xx <= 8) {
            const float* src = br ? g_grad : g_dct;
            v = src[(b * 3 + c) * 64 + (yy - 1) * 8 + (xx - 1)];
        }
        tile[br][c][yy][xx] = v;
    }
    __syncthreads();

    const int co = tid >> 2;
    const int q  = tid & 3;

    const float rs = rsqrtf(1.0f + 1e-5f);
    const float kd  = bg_d[co] * rs;
    const float bd  = cb_d[co] * kd + bb_d[co];
    const float kg  = bg_g[co] * rs;
    const float bgc = cb_g[co] * kg + bb_g[co];

    float dvals[16], gvals[16];

    {
        float wr[27];
#pragma unroll
        for (int i = 0; i < 27; i++) wr[i] = cw_d[co * 27 + i];
#pragma unroll
        for (int i = 0; i < 16; i++) {
            int cell = q * 16 + i;
            int y = cell >> 3, xx0 = cell & 7;
            float a = 0.0f;
#pragma unroll
            for (int ci = 0; ci < 3; ci++)
#pragma unroll
                for (int ky = 0; ky < 3; ky++)
#pragma unroll
                    for (int kx = 0; kx < 3; kx++)
                        a = fmaf(tile[0][ci][y + ky][xx0 + kx], wr[ci * 9 + ky * 3 + kx], a);
            dvals[i] = fmaxf(fmaf(a, kd, bd), 0.0f);
        }
    }
    {
        float wr[27];
#pragma unroll
        for (int i = 0; i < 27; i++) wr[i] = cw_g[co * 27 + i];
#pragma unroll
        for (int i = 0; i < 16; i++) {
            int cell = q * 16 + i;
            int y = cell >> 3, xx0 = cell & 7;
            float a = 0.0f;
#pragma unroll
            for (int ci = 0; ci < 3; ci++)
#pragma unroll
                for (int ky = 0; ky < 3; ky++)
#pragma unroll
                    for (int kx = 0; kx < 3; kx++)
                        a = fmaf(tile[1][ci][y + ky][xx0 + kx], wr[ci * 9 + ky * 3 + kx], a);
            gvals[i] = fmaxf(fmaf(a, kg, bgc), 0.0f);
        }
    }

    float psum = 0.0f;
#pragma unroll
    for (int i = 0; i < 16; i++) psum += dvals[i] + gvals[i];
    red[tid] = psum;

    float aD0 = 0.f, aD1 = 0.f, aG0 = 0.f, aG1 = 0.f;
    const float* __restrict__ c0 = clsw;
    const float* __restrict__ c1 = clsw + 4096;
    const int base = tid * 16;
#pragma unroll
    for (int i = 0; i < 16; i++) {
        float w0 = c0[base + i], w1 = c1[base + i];
        aD0 = fmaf(dvals[i], w0, aD0);
        aD1 = fmaf(dvals[i], w1, aD1);
        aG0 = fmaf(gvals[i], w0, aG0);
        aG1 = fmaf(gvals[i], w1, aG1);
    }
#pragma unroll
    for (int off = 16; off > 0; off >>= 1) {
        aD0 += __shfl_down_sync(0xffffffffu, aD0, off);
        aD1 += __shfl_down_sync(0xffffffffu, aD1, off);
        aG0 += __shfl_down_sync(0xffffffffu, aG0, off);
        aG1 += __shfl_down_sync(0xffffffffu, aG1, off);
    }
    if ((tid & 31) == 0) {
        warpred[tid >> 5][0] = aD0;
        warpred[tid >> 5][1] = aD1;
        warpred[tid >> 5][2] = aG0;
        warpred[tid >> 5][3] = aG1;
    }
    __syncthreads();

    if (tid < 64) {
        float s = red[tid * 4] + red[tid * 4 + 1] + red[tid * 4 + 2] + red[tid * 4 + 3];
        sfw[tid] = (s * (1.0f / 64.0f)) * fw[tid];
    }
    __syncthreads();

    if (tid == 0) {
        float tot = fb[0];
        for (int c2 = 0; c2 < 64; c2++) tot += sfw[c2];
        float w = 1.0f / (1.0f + expf(-tot));
        float D0 = 0.f, D1 = 0.f, G0 = 0.f, G1 = 0.f;
        for (int wd = 0; wd < 8; wd++) {
            D0 += warpred[wd][0];
            D1 += warpred[wd][1];
            G0 += warpred[wd][2];
            G1 += warpred[wd][3];
        }
        out[b * 2 + 0] = w * D0 + (1.0f - w) * G0 + clsb[0];
        out[b * 2 + 1] = w * D1 + (1.0f - w) * G1 + clsb[1];
    }
}

// ---------------------------------------------------------------------------
extern "C" void kernel_launch(void* const* d_in, const int* in_sizes, int n_in,
                              void* d_out, int out_size) {
    const float* x     = (const float*)d_in[0];
    const float* cw_d  = (const float*)d_in[1];
    const float* cb_d  = (const float*)d_in[2];
    const float* bg_d  = (const float*)d_in[3];
    const float* bb_d  = (const float*)d_in[4];
    const float* cw_g  = (const float*)d_in[5];
    const float* cb_g  = (const float*)d_in[6];
    const float* bg_g  = (const float*)d_in[7];
    const float* bb_g  = (const float*)d_in[8];
    const float* fw    = (const float*)d_in[9];
    const float* fb    = (const float*)d_in[10];
    const float* clsw  = (const float*)d_in[11];
    const float* clsb  = (const float*)d_in[12];
    float* out = (float*)d_out;

    dct_grad_kernel<<<384, 256>>>(x);
    head_kernel<<<128, 256>>>(cw_d, cb_d, bg_d, bb_d,
                              cw_g, cb_g, bg_g, bb_g,
                              fw, fb, clsw, clsb, out);
}

// round 7
// speedup vs baseline: 1.0437x; 1.0437x over previous
#include <cuda_runtime.h>
#include <math.h>
#include <stdint.h>

// Scratch (allocation-free rule: __device__ globals)
__device__ float g_dct[128 * 3 * 64];   // dct branch input, (b,c,8,8)
__device__ float g_grad[128 * 3 * 64];  // grad branch input, (b,c,8,8)

__device__ __forceinline__ uint64_t pack2(float lo, float hi) {
    uint64_t r;
    asm("mov.b64 %0, {%1, %2};" : "=l"(r) : "r"(__float_as_uint(lo)), "r"(__float_as_uint(hi)));
    return r;
}
__device__ __forceinline__ void unpack2(float& lo, float& hi, uint64_t v) {
    uint32_t a, b;
    asm("mov.b64 {%0, %1}, %2;" : "=r"(a), "=r"(b) : "l"(v));
    lo = __uint_as_float(a); hi = __uint_as_float(b);
}
__device__ __forceinline__ uint64_t fma2(uint64_t a, uint64_t b, uint64_t c) {
    uint64_t d;
    asm("fma.rn.f32x2 %0, %1, %2, %3;" : "=l"(d) : "l"(a), "l"(b), "l"(c));
    return d;
}

// ---------------------------------------------------------------------------
// Kernel 1: per (b,c) image: dct_in = A x A^T  and sampled-Sobel grad_in.
// grid = 384 (= 128*3), block = 256  (unchanged from R6)
// ---------------------------------------------------------------------------
__global__ void __launch_bounds__(256) dct_grad_kernel(const float* __restrict__ x) {
    __shared__ float    Rf2[8][25];
    __shared__ uint64_t Asd[256][8];       // A duplicated pairs (a,a)  (16 KB)
    __shared__ float    As2[8][256];       // A row-major for pass 2    (8 KB)
    __shared__ float    Tp[4][8][256];     // team partials / Ts        (32 KB)

    const int tid = threadIdx.x;
    const int blk = blockIdx.x;
    const float* __restrict__ xc = x + (size_t)blk * 65536;

    // --- inline A computation -------------------------------------------
    if (tid < 200) {
        const int o = tid / 25, k = tid % 25;
        float sk = (k == 0) ? sqrtf(1.0f / 256.0f) : sqrtf(2.0f / 256.0f);
        float si = sqrtf(2.0f / 256.0f);
        float tw = (float)(2 * k + 1) * (1.0f / 512.0f);   // exact
        float c0 = cospif(tw * (float)(32 * o + 15));
        float c1 = cospif(tw * (float)(32 * o + 16));
        Rf2[o][k] = 0.5f * si * sk * (c0 + c1);
    }
    __syncthreads();
    {
        const float th = (float)(2 * tid + 1) * (1.0f / 512.0f);  // exact
        float cp = cospif(th);
        const float twoc = 2.0f * cp;
        float cpp = 1.0f;
        float a[8];
#pragma unroll
        for (int o = 0; o < 8; o++) a[o] = fmaf(Rf2[o][1], cp, Rf2[o][0]);
#pragma unroll
        for (int k = 2; k < 25; k++) {
            float ck = fmaf(twoc, cp, -cpp);
#pragma unroll
            for (int o = 0; o < 8; o++) a[o] = fmaf(Rf2[o][k], ck, a[o]);
            cpp = cp; cp = ck;
        }
#pragma unroll
        for (int o = 0; o < 8; o++) {
            As2[o][tid] = a[o];
            Asd[tid][o] = pack2(a[o], a[o]);
        }
    }
    __syncthreads();

    // --- pass 1: T = A @ X, f32x2 packed FMA ----------------------------
    const int team = tid >> 6;
    const int t64  = tid & 63;

    uint64_t acc2[8][2];
#pragma unroll
    for (int o = 0; o < 8; o++) { acc2[o][0] = 0ull; acc2[o][1] = 0ull; }

    const int mbase = team * 64;
#pragma unroll 8
    for (int mm = 0; mm < 64; mm++) {
        const int m = mbase + mm;
        float4 xv = reinterpret_cast<const float4*>(xc + (size_t)m * 256)[t64];
        uint64_t x01 = pack2(xv.x, xv.y);
        uint64_t x23 = pack2(xv.z, xv.w);
        ulonglong2 d01 = *reinterpret_cast<const ulonglong2*>(&Asd[m][0]);
        ulonglong2 d23 = *reinterpret_cast<const ulonglong2*>(&Asd[m][2]);
        ulonglong2 d45 = *reinterpret_cast<const ulonglong2*>(&Asd[m][4]);
        ulonglong2 d67 = *reinterpret_cast<const ulonglong2*>(&Asd[m][6]);
        acc2[0][0] = fma2(d01.x, x01, acc2[0][0]);
        acc2[0][1] = fma2(d01.x, x23, acc2[0][1]);
        acc2[1][0] = fma2(d01.y, x01, acc2[1][0]);
        acc2[1][1] = fma2(d01.y, x23, acc2[1][1]);
        acc2[2][0] = fma2(d23.x, x01, acc2[2][0]);
        acc2[2][1] = fma2(d23.x, x23, acc2[2][1]);
        acc2[3][0] = fma2(d23.y, x01, acc2[3][0]);
        acc2[3][1] = fma2(d23.y, x23, acc2[3][1]);
        acc2[4][0] = fma2(d45.x, x01, acc2[4][0]);
        acc2[4][1] = fma2(d45.x, x23, acc2[4][1]);
        acc2[5][0] = fma2(d45.y, x01, acc2[5][0]);
        acc2[5][1] = fma2(d45.y, x23, acc2[5][1]);
        acc2[6][0] = fma2(d67.x, x01, acc2[6][0]);
        acc2[6][1] = fma2(d67.x, x23, acc2[6][1]);
        acc2[7][0] = fma2(d67.y, x01, acc2[7][0]);
        acc2[7][1] = fma2(d67.y, x23, acc2[7][1]);
    }
#pragma unroll
    for (int o = 0; o < 8; o++) {
        float4 v;
        unpack2(v.x, v.y, acc2[o][0]);
        unpack2(v.z, v.w, acc2[o][1]);
        *reinterpret_cast<float4*>(&Tp[team][o][t64 * 4]) = v;
    }
    __syncthreads();

    float* TsF = &Tp[0][0][0];   // Ts[o][c] = TsF[o*256 + c]
    {
        float s[8];
#pragma unroll
        for (int o = 0; o < 8; o++)
            s[o] = Tp[0][o][tid] + Tp[1][o][tid] + Tp[2][o][tid] + Tp[3][o][tid];
#pragma unroll
        for (int o = 0; o < 8; o++) TsF[o * 256 + tid] = s[o];
    }
    __syncthreads();

    // --- pass 2: out = Ts @ A^T, 4 partials per output ------------------
    {
        const int outp = tid >> 2;
        const int part = tid & 3;
        const int oy = outp >> 3, ox = outp & 7;
        const float* __restrict__ tsr = TsF + oy * 256;
        const float* __restrict__ ar  = &As2[ox][0];
        float s = 0.0f;
        const int rot = (4 * outp + part) & 63;
#pragma unroll 8
        for (int i = 0; i < 64; i++) {
            int j = part * 64 + ((i + rot) & 63);
            s = fmaf(tsr[j], ar[j], s);
        }
        s += __shfl_xor_sync(0xffffffffu, s, 1);
        s += __shfl_xor_sync(0xffffffffu, s, 2);
        if (part == 0) g_dct[blk * 64 + outp] = s;
    }

    // --- Sobel ----------------------------------------------------------
    {
        const int cell = tid >> 2;
        const int pt = tid & 3;
        const int r = 32 * (cell >> 3) + 15 + (pt >> 1);
        const int c = 32 * (cell & 7) + 15 + (pt & 1);
        float p[3][3];
#pragma unroll
        for (int a = 0; a < 3; a++)
#pragma unroll
            for (int b = 0; b < 3; b++)
                p[a][b] = xc[(r - 1 + a) * 256 + (c - 1 + b)];
        float gx = (p[0][2] - p[0][0])
                 + 2.0f * (p[1][2] - p[1][0])
                 + (p[2][2] - p[2][0]);
        float gy = (p[2][0] - p[0][0])
                 + 2.0f * (p[2][1] - p[0][1])
                 + (p[2][2] - p[0][2]);
        float mag = sqrtf(gx * gx + gy * gy);
        mag += __shfl_xor_sync(0xffffffffu, mag, 1);
        mag += __shfl_xor_sync(0xffffffffu, mag, 2);
        if (pt == 0) g_grad[blk * 64 + cell] = 0.25f * mag;
    }
}

// ---------------------------------------------------------------------------
// Kernel 2: conv3x3 + BN + ReLU on both branches, fusion gate, classifier.
// grid = 128 (one block per batch), block = 512 (thread = (co, out-row))
// ---------------------------------------------------------------------------
__global__ void __launch_bounds__(512) head_kernel(
    const float* __restrict__ cw_d, const float* __restrict__ cb_d,
    const float* __restrict__ bg_d, const float* __restrict__ bb_d,
    const float* __restrict__ cw_g, const float* __restrict__ cb_g,
    const float* __restrict__ bg_g, const float* __restrict__ bb_g,
    const float* __restrict__ fw, const float* __restrict__ fb,
    const float* __restrict__ clsw, const float* __restrict__ clsb,
    float* __restrict__ out)
{
    __shared__ float tile[2][3][10][10];   // zero-padded inputs
    __shared__ float wsm[2][64][28];       // conv weights, padded 27->28 (14 KB)
    __shared__ float red[512];
    __shared__ float warpred[16][4];
    __shared__ float sfw[64];

    const int b = blockIdx.x;
    const int tid = threadIdx.x;

    // Stage conv weights (1728 floats per branch) into smem.
    for (int t = tid; t < 64 * 27; t += 512) {
        int co_ = t / 27, i_ = t % 27;
        wsm[0][co_][i_] = cw_d[t];
        wsm[1][co_][i_] = cw_g[t];
    }
    // Stage zero-padded input tiles.
    for (int t = tid; t < 600; t += 512) {
        int br = t / 300, rem = t % 300;
        int c = rem / 100, yy = (rem % 100) / 10, xx = rem % 10;
        float v = 0.0f;
        if (yy >= 1 && yy <= 8 && xx >= 1 && xx <= 8) {
            const float* src = br ? g_grad : g_dct;
            v = src[(b * 3 + c) * 64 + (yy - 1) * 8 + (xx - 1)];
        }
        tile[br][c][yy][xx] = v;
    }
    __syncthreads();

    const int co = tid >> 3;   // 0..63  output channel
    const int oy = tid & 7;    // 0..7   output row (8 cells along x)

    const float rs = rsqrtf(1.0f + 1e-5f);
    const float kd  = bg_d[co] * rs;
    const float bd  = cb_d[co] * kd + bb_d[co];
    const float kg  = bg_g[co] * rs;
    const float bgc = cb_g[co] * kg + bb_g[co];

    float dv[8], gv[8];
    {
        const float* wr = &wsm[0][co][0];
#pragma unroll
        for (int i = 0; i < 8; i++) {
            float a = 0.0f;
#pragma unroll
            for (int ci = 0; ci < 3; ci++)
#pragma unroll
                for (int ky = 0; ky < 3; ky++)
#pragma unroll
                    for (int kx = 0; kx < 3; kx++)
                        a = fmaf(tile[0][ci][oy + ky][i + kx], wr[ci * 9 + ky * 3 + kx], a);
            dv[i] = fmaxf(fmaf(a, kd, bd), 0.0f);
        }
    }
    {
        const float* wr = &wsm[1][co][0];
#pragma unroll
        for (int i = 0; i < 8; i++) {
            float a = 0.0f;
#pragma unroll
            for (int ci = 0; ci < 3; ci++)
#pragma unroll
                for (int ky = 0; ky < 3; ky++)
#pragma unroll
                    for (int kx = 0; kx < 3; kx++)
                        a = fmaf(tile[1][ci][oy + ky][i + kx], wr[ci * 9 + ky * 3 + kx], a);
            gv[i] = fmaxf(fmaf(a, kg, bgc), 0.0f);
        }
    }

    // gate partial
    float psum = 0.0f;
#pragma unroll
    for (int i = 0; i < 8; i++) psum += dv[i] + gv[i];
    red[tid] = psum;

    // classifier partials: flat = co*64 + oy*8 + i = tid*8 + i  (float4 loads)
    float aD0, aD1, aG0, aG1;
    {
        const float4* __restrict__ c0 = reinterpret_cast<const float4*>(clsw) + tid * 2;
        const float4* __restrict__ c1 = reinterpret_cast<const float4*>(clsw + 4096) + tid * 2;
        float4 w00 = c0[0], w01 = c0[1];
        float4 w10 = c1[0], w11 = c1[1];
        aD0 = dv[0]*w00.x + dv[1]*w00.y + dv[2]*w00.z + dv[3]*w00.w
            + dv[4]*w01.x + dv[5]*w01.y + dv[6]*w01.z + dv[7]*w01.w;
        aD1 = dv[0]*w10.x + dv[1]*w10.y + dv[2]*w10.z + dv[3]*w10.w
            + dv[4]*w11.x + dv[5]*w11.y + dv[6]*w11.z + dv[7]*w11.w;
        aG0 = gv[0]*w00.x + gv[1]*w00.y + gv[2]*w00.z + gv[3]*w00.w
            + gv[4]*w01.x + gv[5]*w01.y + gv[6]*w01.z + gv[7]*w01.w;
        aG1 = gv[0]*w10.x + gv[1]*w10.y + gv[2]*w10.z + gv[3]*w10.w
            + gv[4]*w11.x + gv[5]*w11.y + gv[6]*w11.z + gv[7]*w11.w;
    }
#pragma unroll
    for (int off = 16; off > 0; off >>= 1) {
        aD0 += __shfl_down_sync(0xffffffffu, aD0, off);
        aD1 += __shfl_down_sync(0xffffffffu, aD1, off);
        aG0 += __shfl_down_sync(0xffffffffu, aG0, off);
        aG1 += __shfl_down_sync(0xffffffffu, aG1, off);
    }
    if ((tid & 31) == 0) {
        warpred[tid >> 5][0] = aD0;
        warpred[tid >> 5][1] = aD1;
        warpred[tid >> 5][2] = aG0;
        warpred[tid >> 5][3] = aG1;
    }
    __syncthreads();

    if (tid < 64) {
        float s = 0.0f;
#pragma unroll
        for (int k = 0; k < 8; k++) s += red[tid * 8 + k];
        sfw[tid] = (s * (1.0f / 64.0f)) * fw[tid];
    }
    __syncthreads();

    if (tid == 0) {
        float tot = fb[0];
#pragma unroll
        for (int c2 = 0; c2 < 64; c2++) tot += sfw[c2];
        float w = 1.0f / (1.0f + expf(-tot));
        float D0 = 0.f, D1 = 0.f, G0 = 0.f, G1 = 0.f;
#pragma unroll
        for (int wd = 0; wd < 16; wd++) {
            D0 += warpred[wd][0];
            D1 += warpred[wd][1];
            G0 += warpred[wd][2];
            G1 += warpred[wd][3];
        }
        out[b * 2 + 0] = w * D0 + (1.0f - w) * G0 + clsb[0];
        out[b * 2 + 1] = w * D1 + (1.0f - w) * G1 + clsb[1];
    }
}

// ---------------------------------------------------------------------------
extern "C" void kernel_launch(void* const* d_in, const int* in_sizes, int n_in,
                              void* d_out, int out_size) {
    const float* x     = (const float*)d_in[0];
    const float* cw_d  = (const float*)d_in[1];
    const float* cb_d  = (const float*)d_in[2];
    const float* bg_d  = (const float*)d_in[3];
    const float* bb_d  = (const float*)d_in[4];
    const float* cw_g  = (const float*)d_in[5];
    const float* cb_g  = (const float*)d_in[6];
    const float* bg_g  = (const float*)d_in[7];
    const float* bb_g  = (const float*)d_in[8];
    const float* fw    = (const float*)d_in[9];
    const float* fb    = (const float*)d_in[10];
    const float* clsw  = (const float*)d_in[11];
    const float* clsb  = (const float*)d_in[12];
    float* out = (float*)d_out;

    dct_grad_kernel<<<384, 256>>>(x);
    head_kernel<<<128, 512>>>(cw_d, cb_d, bg_d, bb_d,
                              cw_g, cb_g, bg_g, bb_g,
                              fw, fb, clsw, clsb, out);
}